// round 2
// baseline (speedup 1.0000x reference)
#include <cuda_runtime.h>
#include <cuda_bf16.h>
#include <cstdint>

// Problem constants (fixed by the dataset)
#define D        144            // feature dim
#define DQ       36             // D / 4 (float4 chunks)
#define NROWS    4096           // 4 * 1024
#define NCODES   50257
#define BR       64             // rows per CTA tile
#define BC       128            // codes per inner tile
#define TILES    ((NCODES + BC - 1) / BC)   // 393
#define SPLITS   8
#define TPS      ((TILES + SPLITS - 1) / SPLITS)  // 50
#define ZQ_ELEMS (NROWS * D)    // 589824

// Scratch (no cudaMalloc allowed)
__device__ unsigned long long g_best[NROWS];
__device__ float g_nrm[NCODES];   // ||e_j||^2 (fp32)
__device__ float g_zn[NROWS];     // ||z_row||^2 (fp32)
__device__ float g_part[NROWS];

// Dynamic smem layout (floats):
//   zT  [D][BR]   = 144*64  = 9216
//   eT  [D][BC]   = 144*128 = 18432
//   nrm [BC]      = 128
#define SMEM_FLOATS (D*BR + D*BC + BC)
#define SMEM_BYTES  (SMEM_FLOATS * 4)

#define FMA2(acc, a, b) \
    asm("fma.rn.f32x2 %0, %1, %2, %0;" : "+l"(acc) : "l"(a), "l"(b))
#define PACKDUP(out, f) \
    asm("mov.b64 %0, {%1, %1};" : "=l"(out) : "r"(__float_as_uint(f)))

__device__ __forceinline__ unsigned ordered_bits(float s) {
    unsigned b = __float_as_uint(s);
    return b ^ ((unsigned)((int)b >> 31) | 0x80000000u);
}

// ---------------------------------------------------------------------------
// Kernel 1: per-code norms, per-row z norms, reset best keys
// ---------------------------------------------------------------------------
__global__ void prep_kernel(const float* __restrict__ z,
                            const float* __restrict__ emb) {
    int t = blockIdx.x * 256 + threadIdx.x;
    if (t < NROWS) {
        g_best[t] = 0xFFFFFFFFFFFFFFFFull;
        const float4* p = (const float4*)(z + (size_t)t * D);
        float s = 0.f;
        #pragma unroll
        for (int i = 0; i < DQ; i++) {
            float4 v = p[i];
            s += v.x * v.x + v.y * v.y + v.z * v.z + v.w * v.w;
        }
        g_zn[t] = s;
    }
    if (t < NCODES) {
        const float4* p = (const float4*)(emb + (size_t)t * D);
        float s = 0.f;
        #pragma unroll
        for (int i = 0; i < DQ; i++) {
            float4 v = p[i];
            s += v.x * v.x + v.y * v.y + v.z * v.z + v.w * v.w;
        }
        g_nrm[t] = s;
    }
}

// ---------------------------------------------------------------------------
// Kernel 2: fused distance-GEMM + argmin, replicating the reference's fp32
// quantization: s = fl( fl(||z||^2 + ||e||^2) - 2*dot ).
// grid = (NROWS/BR, SPLITS), block = 256, dyn smem = SMEM_BYTES
// ---------------------------------------------------------------------------
__global__ void __launch_bounds__(256, 2)
argmin_kernel(const float* __restrict__ z, const float* __restrict__ emb) {
    extern __shared__ float sm[];
    float* zT  = sm;                 // [k][row]
    float* eT  = sm + D * BR;        // [k][code]
    float* nrmT = eT + D * BC;       // [code]

    const int tid = threadIdx.x;
    const int tx = tid & 15;         // code group
    const int ty = tid >> 4;         // row group
    const int row0 = blockIdx.x * BR;

    // Per-thread z row norms (4 rows)
    float zn[4];
    #pragma unroll
    for (int r = 0; r < 4; r++) zn[r] = g_zn[row0 + ty * 4 + r];

    // Load z tile transposed: zT[k][row]
    for (int i = tid; i < BR * DQ; i += 256) {
        int row = i & (BR - 1);
        int kq  = i >> 6;
        float4 v = *(const float4*)(z + (size_t)(row0 + row) * D + kq * 4);
        zT[(kq * 4 + 0) * BR + row] = v.x;
        zT[(kq * 4 + 1) * BR + row] = v.y;
        zT[(kq * 4 + 2) * BR + row] = v.z;
        zT[(kq * 4 + 3) * BR + row] = v.w;
    }

    const int tile0 = blockIdx.y * TPS;
    const int tile1 = min(tile0 + TPS, TILES);

    float    bestS[4];
    unsigned bestI[4];
    #pragma unroll
    for (int r = 0; r < 4; r++) { bestS[r] = __int_as_float(0x7f800000); bestI[r] = 0u; }

    const float* zrow = zT + ty * 4;
    const float* erow = eT + tx * 8;

    for (int t = tile0; t < tile1; ++t) {
        const int c0 = t * BC;
        __syncthreads();   // previous-iter readers done before overwrite

        // Load e tile transposed: eT[k][code] (OOB codes -> 0)
        for (int i = tid; i < BC * DQ; i += 256) {
            int code = i & (BC - 1);
            int kq   = i >> 7;
            int gc   = c0 + code;
            float4 v = make_float4(0.f, 0.f, 0.f, 0.f);
            if (gc < NCODES)
                v = *(const float4*)(emb + (size_t)gc * D + kq * 4);
            eT[(kq * 4 + 0) * BC + code] = v.x;
            eT[(kq * 4 + 1) * BC + code] = v.y;
            eT[(kq * 4 + 2) * BC + code] = v.z;
            eT[(kq * 4 + 3) * BC + code] = v.w;
        }
        if (tid < BC) {
            int gc = c0 + tid;
            nrmT[tid] = (gc < NCODES) ? g_nrm[gc] : __int_as_float(0x7f800000);
        }
        __syncthreads();

        // 4 rows x 8 codes accumulation, packed f32x2 (2 codes per reg)
        unsigned long long acc[16];
        #pragma unroll
        for (int i = 0; i < 16; i++) acc[i] = 0ull;  // (0.f, 0.f)

        #pragma unroll 4
        for (int k = 0; k < D; ++k) {
            float4 zv = *(const float4*)(zrow + k * BR);
            ulonglong2 ea = *(const ulonglong2*)(erow + k * BC);
            ulonglong2 eb = *(const ulonglong2*)(erow + k * BC + 4);
            unsigned long long z0, z1, z2, z3;
            PACKDUP(z0, zv.x); PACKDUP(z1, zv.y);
            PACKDUP(z2, zv.z); PACKDUP(z3, zv.w);
            FMA2(acc[ 0], z0, ea.x); FMA2(acc[ 1], z0, ea.y);
            FMA2(acc[ 2], z0, eb.x); FMA2(acc[ 3], z0, eb.y);
            FMA2(acc[ 4], z1, ea.x); FMA2(acc[ 5], z1, ea.y);
            FMA2(acc[ 6], z1, eb.x); FMA2(acc[ 7], z1, eb.y);
            FMA2(acc[ 8], z2, ea.x); FMA2(acc[ 9], z2, ea.y);
            FMA2(acc[10], z2, eb.x); FMA2(acc[11], z2, eb.y);
            FMA2(acc[12], z3, ea.x); FMA2(acc[13], z3, ea.y);
            FMA2(acc[14], z3, eb.x); FMA2(acc[15], z3, eb.y);
        }

        // Epilogue: s = fl( fl(zn + ||e||^2) - 2*dot ), running min
        // (earliest index on tie — matches jnp.argmin on the quantized d)
        #pragma unroll
        for (int r = 0; r < 4; r++) {
            #pragma unroll
            for (int c = 0; c < 4; c++) {
                unsigned long long a = acc[r * 4 + c];
                float d0 = __uint_as_float((unsigned)(a & 0xFFFFFFFFull));
                float d1 = __uint_as_float((unsigned)(a >> 32));
                int j = tx * 8 + c * 2;
                float t0 = __fadd_rn(zn[r], nrmT[j]);
                float t1 = __fadd_rn(zn[r], nrmT[j + 1]);
                float s0 = __fmaf_rn(d0, -2.f, t0);  // single-rounded t - 2d
                float s1 = __fmaf_rn(d1, -2.f, t1);
                unsigned gc = (unsigned)(c0 + j);
                if (s0 < bestS[r]) { bestS[r] = s0; bestI[r] = gc; }
                if (s1 < bestS[r]) { bestS[r] = s1; bestI[r] = gc + 1; }
            }
        }
    }

    // Reduce across tx (16 consecutive lanes = half-warp), then global merge.
    #pragma unroll
    for (int r = 0; r < 4; r++) {
        unsigned long long key =
            ((unsigned long long)ordered_bits(bestS[r]) << 32) | bestI[r];
        #pragma unroll
        for (int off = 8; off >= 1; off >>= 1) {
            unsigned long long o = __shfl_xor_sync(0xFFFFFFFFu, key, off);
            if (o < key) key = o;
        }
        if (tx == 0)
            atomicMin(&g_best[row0 + ty * 4 + r], key);
    }
}

// ---------------------------------------------------------------------------
// Kernel 3: gather z_q, write index (as float), per-row squared-error partial
// grid = NROWS, block = 128
// ---------------------------------------------------------------------------
__global__ void gather_kernel(const float* __restrict__ z,
                              const float* __restrict__ emb,
                              float* __restrict__ out) {
    const int row = blockIdx.x;
    const int tid = threadIdx.x;
    const unsigned idx = (unsigned)(g_best[row] & 0xFFFFFFFFull);
    const float* e  = emb + (size_t)idx * D;
    const float* zr = z + (size_t)row * D;
    float* o = out + (size_t)row * D;

    float s = 0.f;
    for (int d = tid; d < D; d += 128) {
        float q = e[d];
        o[d] = q;
        float df = q - zr[d];
        s += df * df;
    }
    // block reduce (deterministic)
    #pragma unroll
    for (int off = 16; off >= 1; off >>= 1)
        s += __shfl_xor_sync(0xFFFFFFFFu, s, off);
    __shared__ float ws[4];
    if ((tid & 31) == 0) ws[tid >> 5] = s;
    __syncthreads();
    if (tid == 0) {
        g_part[row] = ws[0] + ws[1] + ws[2] + ws[3];
        out[ZQ_ELEMS + row] = (float)idx;
    }
}

// ---------------------------------------------------------------------------
// Kernel 4: loss = sum(g_part) / (NROWS*D), written to last output element
// ---------------------------------------------------------------------------
__global__ void finalize_kernel(float* __restrict__ out, int out_size) {
    __shared__ float sh[256];
    float s = 0.f;
    for (int i = threadIdx.x; i < NROWS; i += 256) s += g_part[i];
    sh[threadIdx.x] = s;
    __syncthreads();
    for (int off = 128; off >= 1; off >>= 1) {
        if (threadIdx.x < off) sh[threadIdx.x] += sh[threadIdx.x + off];
        __syncthreads();
    }
    if (threadIdx.x == 0)
        out[out_size - 1] = sh[0] / (float)(ZQ_ELEMS);
}

// ---------------------------------------------------------------------------
extern "C" void kernel_launch(void* const* d_in, const int* in_sizes, int n_in,
                              void* d_out, int out_size) {
    const float* z   = (const float*)d_in[0];
    const float* emb = (const float*)d_in[1];
    float* out = (float*)d_out;

    cudaFuncSetAttribute(argmin_kernel,
                         cudaFuncAttributeMaxDynamicSharedMemorySize,
                         SMEM_BYTES);

    prep_kernel<<<(NCODES + 255) / 256, 256>>>(z, emb);
    argmin_kernel<<<dim3(NROWS / BR, SPLITS), 256, SMEM_BYTES>>>(z, emb);
    gather_kernel<<<NROWS, 128>>>(z, emb, out);
    finalize_kernel<<<1, 256>>>(out, out_size);
}

// round 4
// speedup vs baseline: 4.0313x; 4.0313x over previous
#include <cuda_runtime.h>
#include <cuda_bf16.h>
#include <cstdint>

// ===========================================================================
// Problem constants
// ===========================================================================
#define D        144
#define NROWS    4096
#define NCODES   50257
#define ZQ_ELEMS (NROWS * D)

#define BM       128                        // rows per CTA
#define BN       128                        // codes per tile iteration
#define TILES    ((NCODES + BN - 1) / BN)   // 393
#define NSPLIT   9
#define TPS      ((TILES + NSPLIT - 1) / NSPLIT) // 44

#define CAP      4096                       // candidate slots per row
#define CAPW     3e-5f                      // capture window (dot units)
#define ASTRIDE  152                        // A smem row stride (bf16 elems)

// ===========================================================================
// Global scratch (device globals only — no cudaMalloc)
// ===========================================================================
__device__ unsigned long long g_best[NROWS];
__device__ float    g_nrm[NCODES];
__device__ float    g_zn[NROWS];
__device__ float    g_part[NROWS];
__device__ int      g_cnt[NROWS];
__device__ unsigned g_cand[(size_t)NROWS * CAP];
__device__ __align__(16) __nv_bfloat16 g_embh[(size_t)NCODES * D];

__device__ __forceinline__ unsigned ordered_bits(float s) {
    unsigned b = __float_as_uint(s);
    return b ^ ((unsigned)((int)b >> 31) | 0x80000000u);
}
__device__ __forceinline__ unsigned pack_bf16x2(float lo, float hi) {
    __nv_bfloat162 h = __floats2bfloat162_rn(lo, hi);
    return *(unsigned*)&h;
}
__device__ __forceinline__ uint32_t smem_u32(const void* p) {
    uint32_t a;
    asm("{ .reg .u64 t; cvta.to.shared.u64 t, %1; cvt.u32.u64 %0, t; }"
        : "=r"(a) : "l"(p));
    return a;
}
__device__ __forceinline__ void ldsm4(unsigned a[4], unsigned addr) {
    asm volatile("ldmatrix.sync.aligned.m8n8.x4.shared.b16 {%0,%1,%2,%3}, [%4];"
                 : "=r"(a[0]), "=r"(a[1]), "=r"(a[2]), "=r"(a[3]) : "r"(addr));
}
__device__ __forceinline__ void mma16816(float c[4], const unsigned a[4],
                                         const unsigned b[2]) {
    asm volatile(
        "mma.sync.aligned.m16n8k16.row.col.f32.bf16.bf16.f32 "
        "{%0,%1,%2,%3}, {%4,%5,%6,%7}, {%8,%9}, {%0,%1,%2,%3};"
        : "+f"(c[0]), "+f"(c[1]), "+f"(c[2]), "+f"(c[3])
        : "r"(a[0]), "r"(a[1]), "r"(a[2]), "r"(a[3]), "r"(b[0]), "r"(b[1]));
}

// ===========================================================================
// Kernel 1: norms, bf16 emb copy, scratch reset (R2-identical norm arithmetic)
// ===========================================================================
__global__ void prep_kernel(const float* __restrict__ z,
                            const float* __restrict__ emb) {
    int t = blockIdx.x * 256 + threadIdx.x;
    if (t < NROWS) {
        g_best[t] = 0xFFFFFFFFFFFFFFFFull;
        g_cnt[t] = 0;
        const float4* p = (const float4*)(z + (size_t)t * D);
        float s = 0.f;
        #pragma unroll
        for (int i = 0; i < 36; i++) {
            float4 v = p[i];
            s += v.x * v.x + v.y * v.y + v.z * v.z + v.w * v.w;
        }
        g_zn[t] = s;
    }
    if (t < NCODES) {
        const float4* p = (const float4*)(emb + (size_t)t * D);
        uint2* dst = (uint2*)(g_embh + (size_t)t * D);
        float s = 0.f;
        #pragma unroll
        for (int i = 0; i < 36; i++) {
            float4 v = p[i];
            s += v.x * v.x + v.y * v.y + v.z * v.z + v.w * v.w;
            dst[i] = make_uint2(pack_bf16x2(v.x, v.y), pack_bf16x2(v.z, v.w));
        }
        g_nrm[t] = s;
    }
}

// ===========================================================================
// Kernel 2: bf16 mma.sync screening — per-row running max + candidate capture
// grid(32, 9), 256 threads (warps 2m x 4n, warp tile 64x32)
// ===========================================================================
__device__ __forceinline__ void loadB(unsigned b[4][2], int c0, int ks,
                                      int nwarp, int lane) {
    #pragma unroll
    for (int nt = 0; nt < 4; nt++) {
        int code = c0 + nwarp * 32 + nt * 8 + (lane >> 2);
        if (code < NCODES) {
            const __nv_bfloat16* p =
                g_embh + (size_t)code * D + ks * 16 + (lane & 3) * 2;
            b[nt][0] = *(const unsigned*)p;
            b[nt][1] = *(const unsigned*)(p + 8);
        } else {
            b[nt][0] = 0u; b[nt][1] = 0u;
        }
    }
}

__global__ void __launch_bounds__(256, 2)
screen_kernel(const float* __restrict__ z) {
    __shared__ __nv_bfloat16 As[BM * ASTRIDE];

    const int tid  = threadIdx.x;
    const int lane = tid & 31;
    const int wid  = tid >> 5;
    const int mwarp = wid >> 2;       // 0..1
    const int nwarp = wid & 3;        // 0..3
    const int row0 = blockIdx.x * BM;

    // Load z tile -> bf16 smem (row-major, stride 152). 2 threads per row.
    {
        int row = tid >> 1, half = tid & 1;
        const float4* src = (const float4*)(z + (size_t)(row0 + row) * D + half * 72);
        unsigned eo = row * ASTRIDE + half * 72;
        #pragma unroll
        for (int j = 0; j < 18; j++) {
            float4 v = src[j];
            *(uint2*)(As + eo + j * 4) =
                make_uint2(pack_bf16x2(v.x, v.y), pack_bf16x2(v.z, v.w));
        }
    }
    __syncthreads();

    const unsigned asbase = smem_u32(As);
    const int tile0 = blockIdx.y * TPS;
    const int tile1 = min(tile0 + TPS, TILES);

    float rmax[8];
    #pragma unroll
    for (int i = 0; i < 8; i++) rmax[i] = __int_as_float(0xff800000);

    for (int ti = tile0; ti < tile1; ++ti) {
        const int c0 = ti * BN;

        float acc[4][4][4];
        #pragma unroll
        for (int mt = 0; mt < 4; mt++)
            #pragma unroll
            for (int nt = 0; nt < 4; nt++)
                #pragma unroll
                for (int j = 0; j < 4; j++) acc[mt][nt][j] = 0.f;

        unsigned b[4][2], bn[4][2];
        loadB(b, c0, 0, nwarp, lane);

        #pragma unroll
        for (int ks = 0; ks < 9; ks++) {
            if (ks < 8) loadB(bn, c0, ks + 1, nwarp, lane);
            unsigned a[4][4];
            #pragma unroll
            for (int mt = 0; mt < 4; mt++) {
                unsigned arow = mwarp * 64 + mt * 16 + (lane & 15);
                unsigned abyte = (arow * ASTRIDE + ks * 16 + (lane >> 4) * 8) * 2;
                ldsm4(a[mt], asbase + abyte);
            }
            #pragma unroll
            for (int mt = 0; mt < 4; mt++)
                #pragma unroll
                for (int nt = 0; nt < 4; nt++)
                    mma16816(acc[mt][nt], a[mt], b[nt]);
            #pragma unroll
            for (int nt = 0; nt < 4; nt++) {
                b[nt][0] = bn[nt][0]; b[nt][1] = bn[nt][1];
            }
        }

        // Epilogue: per-row running max, then capture within window
        #pragma unroll
        for (int mt = 0; mt < 4; mt++) {
            #pragma unroll
            for (int nt = 0; nt < 4; nt++)
                #pragma unroll
                for (int j = 0; j < 4; j++) {
                    int h = j >> 1;
                    rmax[mt * 2 + h] = fmaxf(rmax[mt * 2 + h], acc[mt][nt][j]);
                }
            #pragma unroll
            for (int nt = 0; nt < 4; nt++)
                #pragma unroll
                for (int j = 0; j < 4; j++) {
                    int h = j >> 1;
                    float v = acc[mt][nt][j];
                    if (v >= rmax[mt * 2 + h] - CAPW) {
                        int c = c0 + nwarp * 32 + nt * 8 + (lane & 3) * 2 + (j & 1);
                        if (c < NCODES) {
                            int r = row0 + mwarp * 64 + mt * 16 + (lane >> 2) + h * 8;
                            int p = atomicAdd(&g_cnt[r], 1);
                            if (p < CAP) g_cand[(size_t)r * CAP + p] = (unsigned)c;
                        }
                    }
                }
        }
        // Pool rmax across the 4 lanes owning the same rows (tig group)
        #pragma unroll
        for (int i = 0; i < 8; i++) {
            float o = __shfl_xor_sync(0xFFFFFFFFu, rmax[i], 1);
            rmax[i] = fmaxf(rmax[i], o);
            o = __shfl_xor_sync(0xFFFFFFFFu, rmax[i], 2);
            rmax[i] = fmaxf(rmax[i], o);
        }
    }
}

// ===========================================================================
// Kernel 3: exact fp32 rescore (bit-identical to R2 scoring semantics)
// ===========================================================================
__global__ void rescore_kernel(const float* __restrict__ z,
                               const float* __restrict__ emb) {
    const int row = blockIdx.x;
    __shared__ float zs[D];
    for (int k = threadIdx.x; k < D; k += 64) zs[k] = z[(size_t)row * D + k];
    __syncthreads();
    const float zn = g_zn[row];
    const int cnt = min(g_cnt[row], CAP);
    for (int i = threadIdx.x; i < cnt; i += 64) {
        unsigned c = g_cand[(size_t)row * CAP + i];
        const float4* e = (const float4*)(emb + (size_t)c * D);
        float acc = 0.f;
        #pragma unroll
        for (int q = 0; q < 36; q++) {
            float4 ev = e[q];
            acc = __fmaf_rn(zs[q * 4 + 0], ev.x, acc);
            acc = __fmaf_rn(zs[q * 4 + 1], ev.y, acc);
            acc = __fmaf_rn(zs[q * 4 + 2], ev.z, acc);
            acc = __fmaf_rn(zs[q * 4 + 3], ev.w, acc);
        }
        float t = __fadd_rn(zn, g_nrm[c]);
        float s = __fmaf_rn(acc, -2.f, t);
        unsigned long long key = ((unsigned long long)ordered_bits(s) << 32) | c;
        atomicMin(&g_best[row], key);
    }
}

// ===========================================================================
// Kernel 4: gather z_q, index, per-row squared-error partial
// ===========================================================================
__global__ void gather_kernel(const float* __restrict__ z,
                              const float* __restrict__ emb,
                              float* __restrict__ out) {
    const int row = blockIdx.x;
    const int tid = threadIdx.x;
    const unsigned idx = (unsigned)(g_best[row] & 0xFFFFFFFFull);
    const float* e  = emb + (size_t)idx * D;
    const float* zr = z + (size_t)row * D;
    float* o = out + (size_t)row * D;

    float s = 0.f;
    for (int d = tid; d < D; d += 128) {
        float q = e[d];
        o[d] = q;
        float df = q - zr[d];
        s += df * df;
    }
    #pragma unroll
    for (int off = 16; off >= 1; off >>= 1)
        s += __shfl_xor_sync(0xFFFFFFFFu, s, off);
    __shared__ float ws[4];
    if ((tid & 31) == 0) ws[tid >> 5] = s;
    __syncthreads();
    if (tid == 0) {
        g_part[row] = ws[0] + ws[1] + ws[2] + ws[3];
        out[ZQ_ELEMS + row] = (float)idx;
    }
}

// ===========================================================================
// Kernel 5: loss
// ===========================================================================
__global__ void finalize_kernel(float* __restrict__ out, int out_size) {
    __shared__ float sh[256];
    float s = 0.f;
    for (int i = threadIdx.x; i < NROWS; i += 256) s += g_part[i];
    sh[threadIdx.x] = s;
    __syncthreads();
    for (int off = 128; off >= 1; off >>= 1) {
        if (threadIdx.x < off) sh[threadIdx.x] += sh[threadIdx.x + off];
        __syncthreads();
    }
    if (threadIdx.x == 0)
        out[out_size - 1] = sh[0] / (float)(ZQ_ELEMS);
}

// ===========================================================================
extern "C" void kernel_launch(void* const* d_in, const int* in_sizes, int n_in,
                              void* d_out, int out_size) {
    const float* z   = (const float*)d_in[0];
    const float* emb = (const float*)d_in[1];
    float* out = (float*)d_out;

    prep_kernel<<<(NCODES + 255) / 256, 256>>>(z, emb);
    screen_kernel<<<dim3(32, NSPLIT), 256>>>(z);
    rescore_kernel<<<NROWS, 64>>>(z, emb);
    gather_kernel<<<NROWS, 128>>>(z, emb, out);
    finalize_kernel<<<1, 256>>>(out, out_size);
}